// round 2
// baseline (speedup 1.0000x reference)
#include <cuda_runtime.h>

#define BN 128
#define PN 24564
#define ON 20
#define CHUNKS 6
#define CHUNK ((PN + CHUNKS - 1) / CHUNKS)   // 4094, 6*4094 = 24564 exactly
#define THRESH 0.5f

// ---- scratch (static device globals; no runtime allocation) ----
__device__ unsigned long long g_bestprior[BN * ON];  // packed (iou_bits<<32)|(~p)
__device__ unsigned char     g_match[BN * PN];       // (best_truth_idx<<1) | pos
__device__ int2              g_poslist[BN * PN];     // compacted positives (b,p)
__device__ int               g_poscount;
__device__ double            g_acc[2];               // loss_l, loss_c

// ---------------------------------------------------------------- init
__global__ void k_init() {
    int i = blockIdx.x * blockDim.x + threadIdx.x;
    if (i < BN * ON) g_bestprior[i] = 0ULL;
    if (i == 0) { g_poscount = 0; g_acc[0] = 0.0; g_acc[1] = 0.0; }
}

// ---------------------------------------------------------------- matching
__global__ __launch_bounds__(256)
void k_match(const float4* __restrict__ priors, const float* __restrict__ gt) {
    __shared__ float4 sbox[ON];
    __shared__ float  sarea[ON];

    const int b   = blockIdx.y;
    const int tid = threadIdx.x;

    if (tid < ON) {
        const float* g = gt + (b * ON + tid) * 5;
        float4 v = make_float4(g[0], g[1], g[2], g[3]);
        sbox[tid]  = v;
        sarea[tid] = (v.z - v.x) * (v.w - v.y);
    }
    __syncthreads();

    float bo[ON];   // best iou per GT (this thread); 0 => untouched
    int   bp[ON];
#pragma unroll
    for (int o = 0; o < ON; o++) { bo[o] = 0.0f; bp[o] = 0; }

    const int p0 = blockIdx.x * CHUNK;
    const int p1 = p0 + CHUNK;   // exact: CHUNKS*CHUNK == PN

    for (int p = p0 + tid; p < p1; p += 256) {
        float4 pr = __ldg(&priors[p]);
        float hx = pr.z * 0.5f, hy = pr.w * 0.5f;
        float px0 = pr.x - hx, py0 = pr.y - hy;
        float px1 = pr.x + hx, py1 = pr.y + hy;
        float ap  = (px1 - px0) * (py1 - py0);

        float maxv = 0.0f; int maxo = 0;
#pragma unroll
        for (int o = 0; o < ON; o++) {
            float4 t = sbox[o];
            float ltx = fmaxf(t.x, px0), lty = fmaxf(t.y, py0);
            float rbx = fminf(t.z, px1), rby = fminf(t.w, py1);
            float w = fmaxf(rbx - ltx, 0.0f);
            float h = fmaxf(rby - lty, 0.0f);
            float inter = w * h;
            float den = sarea[o] + ap - inter;
            float iou = inter * __frcp_rn(den);
            // strict > : first-o wins (jnp.argmax) / smallest-p wins in-thread
            bool gm = iou > maxv;
            maxv = gm ? iou : maxv;
            maxo = gm ? o   : maxo;
            bool gb = iou > bo[o];
            bo[o] = gb ? iou : bo[o];
            bp[o] = gb ? p   : bp[o];
        }
        g_match[b * PN + p] = (unsigned char)((maxo << 1) | (maxv >= THRESH ? 1 : 0));
        if (maxv >= THRESH) {
            int i = atomicAdd(&g_poscount, 1);
            g_poslist[i] = make_int2(b, p);
        }
    }

    // per-warp exact (max iou, min p) reduction, then one atomic per (warp,o)
    const int lane = tid & 31;
#pragma unroll
    for (int o = 0; o < ON; o++) {
        unsigned ib = __float_as_uint(bo[o]);               // iou >= 0 -> monotonic bits
        unsigned m  = __reduce_max_sync(0xFFFFFFFFu, ib);
        unsigned cp = (ib == m) ? (unsigned)bp[o] : 0xFFFFFFFFu;
        unsigned pm = __reduce_min_sync(0xFFFFFFFFu, cp);   // smallest p among ties
        if (lane == 0) {
            unsigned long long key = ((unsigned long long)m << 32)
                                   | (unsigned long long)(0xFFFFFFFFu - pm);
            atomicMax(&g_bestprior[b * ON + o], key);
        }
    }
}

// ---------------------------------------------------------------- override
// one thread per image; sequential o-loop => last-o-wins (mirrors .at[].set)
__global__ void k_override() {
    int b = threadIdx.x;
    if (b < BN) {
        for (int o = 0; o < ON; o++) {
            unsigned long long pk = g_bestprior[b * ON + o];
            unsigned int p = 0xFFFFFFFFu - (unsigned int)(pk & 0xFFFFFFFFull);
            unsigned char old = g_match[b * PN + p];
            if (!(old & 1)) {                         // newly positive -> append once
                int i = atomicAdd(&g_poscount, 1);
                g_poslist[i] = make_int2(b, (int)p);
            }
            g_match[b * PN + p] = (unsigned char)((o << 1) | 1);
        }
    }
}

// ---------------------------------------------------------------- focal (all priors, branch-free)
__device__ __forceinline__ float focal1(float c0, float c1, int cls) {
    // pc = softmax(conf)[cls] = sigmoid(z_cls - z_other)
    float z  = c0 - c1;
    float s  = (cls == 1) ? -z : z;
    float e  = __expf(-s);
    float pc = __frcp_rn(1.0f + e);
    pc = fminf(fmaxf(pc, 1e-7f), 1.0f - 1e-7f);
    float om = 1.0f - pc;
    float fl = 0.25f * (-__logf(pc)) * om * om;
    return (cls < 2) ? fl : 0.0f;   // one_hot outside [0,2) contributes 0
}

__global__ __launch_bounds__(256)
void k_focal(const float4* __restrict__ conf4, const float* __restrict__ gt) {
    __shared__ int   slab[ON];
    __shared__ float swc[8];

    const int b   = blockIdx.y;
    const int tid = threadIdx.x;
    if (tid < ON) slab[tid] = (int)gt[(b * ON + tid) * 5 + 4];
    __syncthreads();

    float sc = 0.0f;
    int q = blockIdx.x * 256 + tid;       // quad of priors
    int p = q * 4;
    if (p < PN) {                          // PN % 4 == 0: full quad or none
        int ix = b * PN + p;
        uchar4 code = *(const uchar4*)&g_match[ix];
        float4 ca = __ldg(&conf4[ix >> 1]);
        float4 cb = __ldg(&conf4[(ix >> 1) + 1]);
        int c0 = (code.x & 1) ? slab[code.x >> 1] + 1 : 0;
        int c1 = (code.y & 1) ? slab[code.y >> 1] + 1 : 0;
        int c2 = (code.z & 1) ? slab[code.z >> 1] + 1 : 0;
        int c3 = (code.w & 1) ? slab[code.w >> 1] + 1 : 0;
        sc  = focal1(ca.x, ca.y, c0);
        sc += focal1(ca.z, ca.w, c1);
        sc += focal1(cb.x, cb.y, c2);
        sc += focal1(cb.z, cb.w, c3);
    }

#pragma unroll
    for (int off = 16; off; off >>= 1) sc += __shfl_down_sync(0xFFFFFFFFu, sc, off);
    if ((tid & 31) == 0) swc[tid >> 5] = sc;
    __syncthreads();
    if (tid == 0) {
        float t = 0.0f;
#pragma unroll
        for (int w = 0; w < 8; w++) t += swc[w];
        atomicAdd(&g_acc[1], (double)t);
    }
}

// ---------------------------------------------------------------- smooth-L1 on compacted positives
__device__ __forceinline__ float smooth_l1(float d) {
    float ad = fabsf(d);
    return (ad < 1.0f) ? 0.5f * d * d : ad - 0.5f;
}

__global__ __launch_bounds__(256)
void k_pos(const float4* __restrict__ loc, const float4* __restrict__ priors,
           const float* __restrict__ gt) {
    __shared__ float swl[8];
    const int n = g_poscount;
    float sl = 0.0f;
    for (int i = blockIdx.x * blockDim.x + threadIdx.x; i < n;
         i += gridDim.x * blockDim.x) {
        int2 e = g_poslist[i];
        int  o = g_match[e.x * PN + e.y] >> 1;
        const float* g = gt + (e.x * ON + o) * 5;
        float4 mb = make_float4(g[0], g[1], g[2], g[3]);
        float4 pr = __ldg(&priors[e.y]);
        float4 ld = __ldg(&loc[e.x * PN + e.y]);
        float iw = __frcp_rn(pr.z);
        float ih = __frcp_rn(pr.w);
        float gx = ((mb.x + mb.z) * 0.5f - pr.x) * 10.0f * iw;
        float gy = ((mb.y + mb.w) * 0.5f - pr.y) * 10.0f * ih;
        float gw = __logf((mb.z - mb.x) * iw) * 5.0f;
        float gh = __logf((mb.w - mb.y) * ih) * 5.0f;
        sl += smooth_l1(ld.x - gx) + smooth_l1(ld.y - gy)
            + smooth_l1(ld.z - gw) + smooth_l1(ld.w - gh);
    }
#pragma unroll
    for (int off = 16; off; off >>= 1) sl += __shfl_down_sync(0xFFFFFFFFu, sl, off);
    int tid = threadIdx.x;
    if ((tid & 31) == 0) swl[tid >> 5] = sl;
    __syncthreads();
    if (tid == 0) {
        float t = 0.0f;
#pragma unroll
        for (int w = 0; w < 8; w++) t += swl[w];
        atomicAdd(&g_acc[0], (double)t);
    }
}

// ---------------------------------------------------------------- finalize
__global__ void k_final(float* out) {
    double np = (double)g_poscount;
    if (np < 1.0) np = 1.0;
    out[0] = (float)(g_acc[0] / np);
    out[1] = (float)(g_acc[1] / np);
}

// ---------------------------------------------------------------- launch
extern "C" void kernel_launch(void* const* d_in, const int* in_sizes, int n_in,
                              void* d_out, int out_size) {
    const float4* loc    = (const float4*)d_in[0];  // [B,P,4] f32
    const float4* conf4  = (const float4*)d_in[1];  // [B,P,2] f32, read as float4 pairs
    const float4* priors = (const float4*)d_in[2];  // [P,4]   f32
    const float*  gt     = (const float*)d_in[3];   // [B,O,5] f32

    k_init<<<(BN * ON + 255) / 256, 256>>>();

    dim3 gm(CHUNKS, BN);
    k_match<<<gm, 256>>>(priors, gt);

    k_override<<<1, 128>>>();

    dim3 gf((PN / 4 + 255) / 256, BN);   // 24 x 128
    k_focal<<<gf, 256>>>(conf4, gt);

    k_pos<<<96, 256>>>(loc, priors, gt);

    k_final<<<1, 1>>>((float*)d_out);
}

// round 3
// speedup vs baseline: 1.0156x; 1.0156x over previous
#include <cuda_runtime.h>

#define BN 128
#define PN 24564
#define ON 20
#define CHUNKS 6
#define CHUNK ((PN + CHUNKS - 1) / CHUNKS)   // 4094, 6*4094 = 24564 exactly
#define THRESH 0.5f

// ---- scratch (static device globals; no runtime allocation) ----
__device__ unsigned long long g_bestprior[BN * ON];  // packed (iou_bits<<32)|(~p)
__device__ unsigned char     g_match[BN * PN];       // (best_truth_idx<<1) | pos
__device__ int2              g_poslist[BN * PN];     // compacted positives (b,p)
__device__ int               g_poscount;
__device__ double            g_acc[2];               // loss_l, loss_c

// ---------------------------------------------------------------- init
__global__ void k_init() {
    int i = blockIdx.x * blockDim.x + threadIdx.x;
    if (i < BN * ON) g_bestprior[i] = 0ULL;
    if (i == 0) { g_poscount = 0; g_acc[0] = 0.0; g_acc[1] = 0.0; }
}

// ---------------------------------------------------------------- matching
__global__ __launch_bounds__(256)
void k_match(const float4* __restrict__ priors, const float* __restrict__ gt) {
    __shared__ float4 sbox[ON];
    __shared__ float  sarea[ON];

    const int b   = blockIdx.y;
    const int tid = threadIdx.x;

    if (tid < ON) {
        const float* g = gt + (b * ON + tid) * 5;
        float4 v = make_float4(g[0], g[1], g[2], g[3]);
        sbox[tid]  = v;
        sarea[tid] = (v.z - v.x) * (v.w - v.y);
    }
    __syncthreads();

    float bo[ON];   // best iou per GT (this thread); 0 => untouched
    int   bp[ON];
#pragma unroll
    for (int o = 0; o < ON; o++) { bo[o] = 0.0f; bp[o] = 0; }

    const int p0 = blockIdx.x * CHUNK;
    const int p1 = p0 + CHUNK;   // exact: CHUNKS*CHUNK == PN

    for (int p = p0 + tid; p < p1; p += 256) {
        float4 pr = __ldg(&priors[p]);
        float hx = pr.z * 0.5f, hy = pr.w * 0.5f;
        float px0 = pr.x - hx, py0 = pr.y - hy;
        float px1 = pr.x + hx, py1 = pr.y + hy;
        float ap  = (px1 - px0) * (py1 - py0);

        float maxv = 0.0f; int maxo = 0;
#pragma unroll
        for (int o = 0; o < ON; o++) {
            float4 t = sbox[o];
            float ltx = fmaxf(t.x, px0), lty = fmaxf(t.y, py0);
            float rbx = fminf(t.z, px1), rby = fminf(t.w, py1);
            float w = fmaxf(rbx - ltx, 0.0f);
            float h = fmaxf(rby - lty, 0.0f);
            float inter = w * h;
            float den = sarea[o] + ap - inter;
            float iou = inter * __frcp_rn(den);
            // strict > : first-o wins (jnp.argmax) / smallest-p wins in-thread
            bool gm = iou > maxv;
            maxv = gm ? iou : maxv;
            maxo = gm ? o   : maxo;
            bool gb = iou > bo[o];
            bo[o] = gb ? iou : bo[o];
            bp[o] = gb ? p   : bp[o];
        }
        g_match[b * PN + p] = (unsigned char)((maxo << 1) | (maxv >= THRESH ? 1 : 0));
        if (maxv >= THRESH) {
            int i = atomicAdd(&g_poscount, 1);
            g_poslist[i] = make_int2(b, p);
        }
    }

    // per-warp exact (max iou, min p) reduction, then one atomic per (warp,o)
    const int lane = tid & 31;
#pragma unroll
    for (int o = 0; o < ON; o++) {
        unsigned ib = __float_as_uint(bo[o]);               // iou >= 0 -> monotonic bits
        unsigned m  = __reduce_max_sync(0xFFFFFFFFu, ib);
        unsigned cp = (ib == m) ? (unsigned)bp[o] : 0xFFFFFFFFu;
        unsigned pm = __reduce_min_sync(0xFFFFFFFFu, cp);   // smallest p among ties
        if (lane == 0) {
            unsigned long long key = ((unsigned long long)m << 32)
                                   | (unsigned long long)(0xFFFFFFFFu - pm);
            atomicMax(&g_bestprior[b * ON + o], key);
        }
    }
}

// ---------------------------------------------------------------- override
// one thread per image; sequential o-loop => last-o-wins (mirrors .at[].set)
__global__ void k_override() {
    int b = threadIdx.x;
    if (b < BN) {
        for (int o = 0; o < ON; o++) {
            unsigned long long pk = g_bestprior[b * ON + o];
            unsigned int p = 0xFFFFFFFFu - (unsigned int)(pk & 0xFFFFFFFFull);
            unsigned char old = g_match[b * PN + p];
            if (!(old & 1)) {                         // newly positive -> append once
                int i = atomicAdd(&g_poscount, 1);
                g_poslist[i] = make_int2(b, (int)p);
            }
            g_match[b * PN + p] = (unsigned char)((o << 1) | 1);
        }
    }
}

// ---------------------------------------------------------------- focal (all priors, branch-free)
__device__ __forceinline__ float focal1(float c0, float c1, int cls) {
    // pc = softmax(conf)[cls] = sigmoid(z_cls - z_other)
    float z  = c0 - c1;
    float s  = (cls == 1) ? -z : z;
    float e  = __expf(-s);
    float pc = __frcp_rn(1.0f + e);
    pc = fminf(fmaxf(pc, 1e-7f), 1.0f - 1e-7f);
    float om = 1.0f - pc;
    float fl = 0.25f * (-__logf(pc)) * om * om;
    return (cls < 2) ? fl : 0.0f;   // one_hot outside [0,2) contributes 0
}

__global__ __launch_bounds__(256)
void k_focal(const float4* __restrict__ conf4, const float* __restrict__ gt) {
    __shared__ int   slab[ON];
    __shared__ float swc[8];

    const int b   = blockIdx.y;
    const int tid = threadIdx.x;
    if (tid < ON) slab[tid] = (int)gt[(b * ON + tid) * 5 + 4];
    __syncthreads();

    float sc = 0.0f;
    int q = blockIdx.x * 256 + tid;       // quad of priors
    int p = q * 4;
    if (p < PN) {                          // PN % 4 == 0: full quad or none
        int ix = b * PN + p;
        uchar4 code = *(const uchar4*)&g_match[ix];
        float4 ca = __ldg(&conf4[ix >> 1]);
        float4 cb = __ldg(&conf4[(ix >> 1) + 1]);
        int c0 = (code.x & 1) ? slab[code.x >> 1] + 1 : 0;
        int c1 = (code.y & 1) ? slab[code.y >> 1] + 1 : 0;
        int c2 = (code.z & 1) ? slab[code.z >> 1] + 1 : 0;
        int c3 = (code.w & 1) ? slab[code.w >> 1] + 1 : 0;
        sc  = focal1(ca.x, ca.y, c0);
        sc += focal1(ca.z, ca.w, c1);
        sc += focal1(cb.x, cb.y, c2);
        sc += focal1(cb.z, cb.w, c3);
    }

#pragma unroll
    for (int off = 16; off; off >>= 1) sc += __shfl_down_sync(0xFFFFFFFFu, sc, off);
    if ((tid & 31) == 0) swc[tid >> 5] = sc;
    __syncthreads();
    if (tid == 0) {
        float t = 0.0f;
#pragma unroll
        for (int w = 0; w < 8; w++) t += swc[w];
        atomicAdd(&g_acc[1], (double)t);
    }
}

// ---------------------------------------------------------------- smooth-L1 on compacted positives
__device__ __forceinline__ float smooth_l1(float d) {
    float ad = fabsf(d);
    return (ad < 1.0f) ? 0.5f * d * d : ad - 0.5f;
}

__global__ __launch_bounds__(256)
void k_pos(const float4* __restrict__ loc, const float4* __restrict__ priors,
           const float* __restrict__ gt) {
    __shared__ float swl[8];
    const int n = g_poscount;
    float sl = 0.0f;
    for (int i = blockIdx.x * blockDim.x + threadIdx.x; i < n;
         i += gridDim.x * blockDim.x) {
        int2 e = g_poslist[i];
        int  o = g_match[e.x * PN + e.y] >> 1;
        const float* g = gt + (e.x * ON + o) * 5;
        float4 mb = make_float4(g[0], g[1], g[2], g[3]);
        float4 pr = __ldg(&priors[e.y]);
        float4 ld = __ldg(&loc[e.x * PN + e.y]);
        float iw = __frcp_rn(pr.z);
        float ih = __frcp_rn(pr.w);
        float gx = ((mb.x + mb.z) * 0.5f - pr.x) * 10.0f * iw;
        float gy = ((mb.y + mb.w) * 0.5f - pr.y) * 10.0f * ih;
        float gw = __logf((mb.z - mb.x) * iw) * 5.0f;
        float gh = __logf((mb.w - mb.y) * ih) * 5.0f;
        sl += smooth_l1(ld.x - gx) + smooth_l1(ld.y - gy)
            + smooth_l1(ld.z - gw) + smooth_l1(ld.w - gh);
    }
#pragma unroll
    for (int off = 16; off; off >>= 1) sl += __shfl_down_sync(0xFFFFFFFFu, sl, off);
    int tid = threadIdx.x;
    if ((tid & 31) == 0) swl[tid >> 5] = sl;
    __syncthreads();
    if (tid == 0) {
        float t = 0.0f;
#pragma unroll
        for (int w = 0; w < 8; w++) t += swl[w];
        atomicAdd(&g_acc[0], (double)t);
    }
}

// ---------------------------------------------------------------- finalize
__global__ void k_final(float* out) {
    double np = (double)g_poscount;
    if (np < 1.0) np = 1.0;
    out[0] = (float)(g_acc[0] / np);
    out[1] = (float)(g_acc[1] / np);
}

// ---------------------------------------------------------------- launch
extern "C" void kernel_launch(void* const* d_in, const int* in_sizes, int n_in,
                              void* d_out, int out_size) {
    const float4* loc    = (const float4*)d_in[0];  // [B,P,4] f32
    const float4* conf4  = (const float4*)d_in[1];  // [B,P,2] f32, read as float4 pairs
    const float4* priors = (const float4*)d_in[2];  // [P,4]   f32
    const float*  gt     = (const float*)d_in[3];   // [B,O,5] f32

    k_init<<<(BN * ON + 255) / 256, 256>>>();

    dim3 gm(CHUNKS, BN);
    k_match<<<gm, 256>>>(priors, gt);

    k_override<<<1, 128>>>();

    dim3 gf((PN / 4 + 255) / 256, BN);   // 24 x 128
    k_focal<<<gf, 256>>>(conf4, gt);

    k_pos<<<96, 256>>>(loc, priors, gt);

    k_final<<<1, 1>>>((float*)d_out);
}

// round 4
// speedup vs baseline: 1.2326x; 1.2136x over previous
#include <cuda_runtime.h>

#define BN 128
#define PN 24564
#define ON 20
#define CHUNKS 6
#define CHUNK ((PN + CHUNKS - 1) / CHUNKS)   // 4094
#define ITERS ((CHUNK + 255) / 256)          // 16
#define THRESH 0.5f

// ---- scratch (static device globals; no runtime allocation) ----
__device__ unsigned long long g_bestprior[BN * ON];  // packed (iou_bits<<32)|(~p)
__device__ unsigned char     g_match[BN * PN];       // (best_truth_idx<<1) | pos
__device__ int2              g_poslist[BN * PN];     // compacted positives (b,p)
__device__ int               g_poscount;
__device__ double            g_acc[2];               // loss_l, loss_c

// ---------------------------------------------------------------- init
__global__ void k_init() {
    int i = blockIdx.x * blockDim.x + threadIdx.x;
    if (i < BN * ON) g_bestprior[i] = 0ULL;
    if (i == 0) { g_poscount = 0; g_acc[0] = 0.0; g_acc[1] = 0.0; }
}

// ---------------------------------------------------------------- matching
__global__ __launch_bounds__(256)
void k_match(const float4* __restrict__ priors, const float* __restrict__ gt) {
    __shared__ float4 sbox[ON];
    __shared__ float  sarea[ON];

    const int b   = blockIdx.y;
    const int tid = threadIdx.x;
    const int lane = tid & 31;

    if (tid < ON) {
        const float* g = gt + (b * ON + tid) * 5;
        float4 v = make_float4(g[0], g[1], g[2], g[3]);
        sbox[tid]  = v;
        sarea[tid] = (v.z - v.x) * (v.w - v.y);
    }
    __syncthreads();

    float bo[ON];   // best iou per GT (this thread); 0 => untouched
    int   bp[ON];
#pragma unroll
    for (int o = 0; o < ON; o++) { bo[o] = 0.0f; bp[o] = 0; }

    const int p0   = blockIdx.x * CHUNK;
    const int pend = (p0 + CHUNK < PN) ? (p0 + CHUNK) : PN;

    for (int k = 0; k < ITERS; k++) {
        int  p     = p0 + k * 256 + tid;
        bool valid = (p < pend);

        // zeroed prior for invalid lanes -> iou computes to exactly 0 everywhere
        float4 pr = __ldg(&priors[valid ? p : 0]);
        if (!valid) pr = make_float4(0.0f, 0.0f, 0.0f, 0.0f);

        float hx = pr.z * 0.5f, hy = pr.w * 0.5f;
        float px0 = pr.x - hx, py0 = pr.y - hy;
        float px1 = pr.x + hx, py1 = pr.y + hy;
        float ap  = (px1 - px0) * (py1 - py0);

        float maxv = 0.0f; int maxo = 0;
#pragma unroll
        for (int o = 0; o < ON; o++) {
            float4 t = sbox[o];
            float ltx = fmaxf(t.x, px0), lty = fmaxf(t.y, py0);
            float rbx = fminf(t.z, px1), rby = fminf(t.w, py1);
            float w = fmaxf(rbx - ltx, 0.0f);
            float h = fmaxf(rby - lty, 0.0f);
            float inter = w * h;
            float den = sarea[o] + ap - inter;
            float iou = __fdividef(inter, den);    // MUFU.RCP + FMUL (fast path)
            // strict > : first-o wins (jnp.argmax) / smallest-p wins in-thread
            bool gm = iou > maxv;
            maxv = gm ? iou : maxv;
            maxo = gm ? o   : maxo;
            bool gb = iou > bo[o];
            bo[o] = gb ? iou : bo[o];
            bp[o] = gb ? p   : bp[o];
        }

        bool pos = maxv >= THRESH;                 // false on invalid (maxv==0)
        if (valid)
            g_match[b * PN + p] = (unsigned char)((maxo << 1) | (pos ? 1 : 0));

        // warp-aggregated positive append: one atomic per warp-iter (usually none)
        unsigned msk = __ballot_sync(0xFFFFFFFFu, pos);
        if (msk) {
            int leader = __ffs(msk) - 1;
            int base = 0;
            if (lane == leader) base = atomicAdd(&g_poscount, __popc(msk));
            base = __shfl_sync(0xFFFFFFFFu, base, leader);
            if (pos) {
                int r = __popc(msk & ((1u << lane) - 1u));
                g_poslist[base + r] = make_int2(b, p);
            }
        }
    }

    // per-warp exact (max iou, min p) reduction, then one atomic per (warp,o)
#pragma unroll
    for (int o = 0; o < ON; o++) {
        unsigned ib = __float_as_uint(bo[o]);               // iou >= 0 -> monotonic bits
        unsigned m  = __reduce_max_sync(0xFFFFFFFFu, ib);
        unsigned cp = (ib == m) ? (unsigned)bp[o] : 0xFFFFFFFFu;
        unsigned pm = __reduce_min_sync(0xFFFFFFFFu, cp);   // smallest p among ties
        if (lane == 0) {
            unsigned long long key = ((unsigned long long)m << 32)
                                   | (unsigned long long)(0xFFFFFFFFu - pm);
            atomicMax(&g_bestprior[b * ON + o], key);
        }
    }
}

// ---------------------------------------------------------------- override
// one thread per image; sequential o-loop => last-o-wins (mirrors .at[].set)
__global__ void k_override() {
    int b = threadIdx.x;
    if (b < BN) {
        for (int o = 0; o < ON; o++) {
            unsigned long long pk = g_bestprior[b * ON + o];
            unsigned int p = 0xFFFFFFFFu - (unsigned int)(pk & 0xFFFFFFFFull);
            unsigned char old = g_match[b * PN + p];
            if (!(old & 1)) {                         // newly positive -> append once
                int i = atomicAdd(&g_poscount, 1);
                g_poslist[i] = make_int2(b, (int)p);
            }
            g_match[b * PN + p] = (unsigned char)((o << 1) | 1);
        }
    }
}

// ---------------------------------------------------------------- focal (all priors, branch-free)
__device__ __forceinline__ float focal1(float c0, float c1, int cls) {
    // pc = softmax(conf)[cls] = sigmoid(z_cls - z_other)
    float z  = c0 - c1;
    float s  = (cls == 1) ? -z : z;
    float e  = __expf(-s);
    float pc = __fdividef(1.0f, 1.0f + e);
    pc = fminf(fmaxf(pc, 1e-7f), 1.0f - 1e-7f);
    float om = 1.0f - pc;
    float fl = 0.25f * (-__logf(pc)) * om * om;
    return (cls < 2) ? fl : 0.0f;   // one_hot outside [0,2) contributes 0
}

__global__ __launch_bounds__(256)
void k_focal(const float4* __restrict__ conf4, const float* __restrict__ gt) {
    __shared__ int   slab[ON];
    __shared__ float swc[8];

    const int b   = blockIdx.y;
    const int tid = threadIdx.x;
    if (tid < ON) slab[tid] = (int)gt[(b * ON + tid) * 5 + 4];
    __syncthreads();

    float sc = 0.0f;
    int q = blockIdx.x * 256 + tid;       // quad of priors
    int p = q * 4;
    if (p < PN) {                          // PN % 4 == 0: full quad or none
        int ix = b * PN + p;
        uchar4 code = *(const uchar4*)&g_match[ix];
        float4 ca = __ldg(&conf4[ix >> 1]);
        float4 cb = __ldg(&conf4[(ix >> 1) + 1]);
        int c0 = (code.x & 1) ? slab[code.x >> 1] + 1 : 0;
        int c1 = (code.y & 1) ? slab[code.y >> 1] + 1 : 0;
        int c2 = (code.z & 1) ? slab[code.z >> 1] + 1 : 0;
        int c3 = (code.w & 1) ? slab[code.w >> 1] + 1 : 0;
        sc  = focal1(ca.x, ca.y, c0);
        sc += focal1(ca.z, ca.w, c1);
        sc += focal1(cb.x, cb.y, c2);
        sc += focal1(cb.z, cb.w, c3);
    }

#pragma unroll
    for (int off = 16; off; off >>= 1) sc += __shfl_down_sync(0xFFFFFFFFu, sc, off);
    if ((tid & 31) == 0) swc[tid >> 5] = sc;
    __syncthreads();
    if (tid == 0) {
        float t = 0.0f;
#pragma unroll
        for (int w = 0; w < 8; w++) t += swc[w];
        atomicAdd(&g_acc[1], (double)t);
    }
}

// ---------------------------------------------------------------- smooth-L1 on compacted positives
__device__ __forceinline__ float smooth_l1(float d) {
    float ad = fabsf(d);
    return (ad < 1.0f) ? 0.5f * d * d : ad - 0.5f;
}

__global__ __launch_bounds__(256)
void k_pos(const float4* __restrict__ loc, const float4* __restrict__ priors,
           const float* __restrict__ gt) {
    __shared__ float swl[8];
    const int n = g_poscount;
    float sl = 0.0f;
    for (int i = blockIdx.x * blockDim.x + threadIdx.x; i < n;
         i += gridDim.x * blockDim.x) {
        int2 e = g_poslist[i];
        int  o = g_match[e.x * PN + e.y] >> 1;
        const float* g = gt + (e.x * ON + o) * 5;
        float4 mb = make_float4(g[0], g[1], g[2], g[3]);
        float4 pr = __ldg(&priors[e.y]);
        float4 ld = __ldg(&loc[e.x * PN + e.y]);
        float iw = __fdividef(1.0f, pr.z);
        float ih = __fdividef(1.0f, pr.w);
        float gx = ((mb.x + mb.z) * 0.5f - pr.x) * 10.0f * iw;
        float gy = ((mb.y + mb.w) * 0.5f - pr.y) * 10.0f * ih;
        float gw = __logf((mb.z - mb.x) * iw) * 5.0f;
        float gh = __logf((mb.w - mb.y) * ih) * 5.0f;
        sl += smooth_l1(ld.x - gx) + smooth_l1(ld.y - gy)
            + smooth_l1(ld.z - gw) + smooth_l1(ld.w - gh);
    }
#pragma unroll
    for (int off = 16; off; off >>= 1) sl += __shfl_down_sync(0xFFFFFFFFu, sl, off);
    int tid = threadIdx.x;
    if ((tid & 31) == 0) swl[tid >> 5] = sl;
    __syncthreads();
    if (tid == 0) {
        float t = 0.0f;
#pragma unroll
        for (int w = 0; w < 8; w++) t += swl[w];
        atomicAdd(&g_acc[0], (double)t);
    }
}

// ---------------------------------------------------------------- finalize
__global__ void k_final(float* out) {
    double np = (double)g_poscount;
    if (np < 1.0) np = 1.0;
    out[0] = (float)(g_acc[0] / np);
    out[1] = (float)(g_acc[1] / np);
}

// ---------------------------------------------------------------- launch
extern "C" void kernel_launch(void* const* d_in, const int* in_sizes, int n_in,
                              void* d_out, int out_size) {
    const float4* loc    = (const float4*)d_in[0];  // [B,P,4] f32
    const float4* conf4  = (const float4*)d_in[1];  // [B,P,2] f32, read as float4 pairs
    const float4* priors = (const float4*)d_in[2];  // [P,4]   f32
    const float*  gt     = (const float*)d_in[3];   // [B,O,5] f32

    k_init<<<(BN * ON + 255) / 256, 256>>>();

    dim3 gm(CHUNKS, BN);
    k_match<<<gm, 256>>>(priors, gt);

    k_override<<<1, 128>>>();

    dim3 gf((PN / 4 + 255) / 256, BN);   // 24 x 128
    k_focal<<<gf, 256>>>(conf4, gt);

    k_pos<<<96, 256>>>(loc, priors, gt);

    k_final<<<1, 1>>>((float*)d_out);
}